// round 4
// baseline (speedup 1.0000x reference)
#include <cuda_runtime.h>
#include <math.h>

#define NN   20000
#define DIN  1024
#define DOU  64
#define NE   320000
#define SZ   (NN*DOU)          // 1,280,000 floats per [N,64] buffer

// Output layout (flattened tuple, float32):
//   hiden_emb [N,64], h [N,1024], ret [N,1], ret_a [N,1], mean [N,1024], disp [N,1024]
#define OFF_HIDEN 0
#define OFF_H     ((size_t)SZ)                       // 1,280,000
#define OFF_RET   (OFF_H + (size_t)NN*DIN)           // 21,760,000
#define OFF_RETA  (OFF_RET + NN)                     // 21,780,000
#define OFF_MEAN  (OFF_RETA + NN)                    // 21,800,000
#define OFF_DISP  (OFF_MEAN + (size_t)NN*DIN)        // 42,280,000

// Scratch: z0, za0, za_acc (emb_a pre-relu), zs_acc (emb_s pre-relu), t = A*z
__device__ float g_z0[SZ];
__device__ float g_za0[SZ];
__device__ float g_zaacc[SZ];
__device__ float g_zsacc[SZ];
__device__ float g_t[SZ];

// ---------------------------------------------------------------------------
// Zero the 4 atomically-accumulated buffers (z lives in d_out, zeroed too)
// ---------------------------------------------------------------------------
__global__ void zero_kernel(float* zout, float* a, float* b, float* c) {
    int i = blockIdx.x * blockDim.x + threadIdx.x;
    int stride = gridDim.x * blockDim.x;
    for (int j = i; j < SZ; j += stride) {
        zout[j] = 0.f; a[j] = 0.f; b[j] = 0.f; c[j] = 0.f;
    }
}

// ---------------------------------------------------------------------------
// C[M,64] = A[M,1024] @ B[1024,64]   (register-tiled fp32 GEMM)
// BM=64, BN=64(full), BK=32, 256 threads, 4x4 micro-tile per thread
// ---------------------------------------------------------------------------
__global__ void gemm_in64(const float* __restrict__ A, const float* __restrict__ B,
                          float* __restrict__ C, int M) {
    __shared__ float As[64][33];
    __shared__ float Bs[32 * 64];

    int tid = threadIdx.x;
    int rowBase = blockIdx.x * 64;
    int tx = tid & 15, ty = tid >> 4;

    float acc[4][4];
#pragma unroll
    for (int i = 0; i < 4; i++)
#pragma unroll
        for (int j = 0; j < 4; j++) acc[i][j] = 0.f;

    int ar = tid >> 2;            // 0..63 : row within tile
    int ak = (tid & 3) << 3;      // 0,8,16,24 : k offset within tile
    bool aval = (rowBase + ar) < M;
    const float* arow = A + (size_t)(rowBase + ar) * DIN + ak;

    for (int k0 = 0; k0 < DIN; k0 += 32) {
        // load A tile (64 x 32)
        float4 v0 = make_float4(0.f, 0.f, 0.f, 0.f);
        float4 v1 = v0;
        if (aval) {
            v0 = *(const float4*)(arow + k0);
            v1 = *(const float4*)(arow + k0 + 4);
        }
        As[ar][ak + 0] = v0.x; As[ar][ak + 1] = v0.y;
        As[ar][ak + 2] = v0.z; As[ar][ak + 3] = v0.w;
        As[ar][ak + 4] = v1.x; As[ar][ak + 5] = v1.y;
        As[ar][ak + 6] = v1.z; As[ar][ak + 7] = v1.w;

        // load B tile (32 x 64) : contiguous 2048 floats
        const float4* bsrc = (const float4*)(B + (size_t)k0 * DOU);
        ((float4*)Bs)[tid]       = bsrc[tid];
        ((float4*)Bs)[tid + 256] = bsrc[tid + 256];

        __syncthreads();

#pragma unroll
        for (int kk = 0; kk < 32; kk++) {
            float a0 = As[ty * 4 + 0][kk];
            float a1 = As[ty * 4 + 1][kk];
            float a2 = As[ty * 4 + 2][kk];
            float a3 = As[ty * 4 + 3][kk];
            float4 bv = *(float4*)&Bs[kk * 64 + tx * 4];
            acc[0][0] = fmaf(a0, bv.x, acc[0][0]); acc[0][1] = fmaf(a0, bv.y, acc[0][1]);
            acc[0][2] = fmaf(a0, bv.z, acc[0][2]); acc[0][3] = fmaf(a0, bv.w, acc[0][3]);
            acc[1][0] = fmaf(a1, bv.x, acc[1][0]); acc[1][1] = fmaf(a1, bv.y, acc[1][1]);
            acc[1][2] = fmaf(a1, bv.z, acc[1][2]); acc[1][3] = fmaf(a1, bv.w, acc[1][3]);
            acc[2][0] = fmaf(a2, bv.x, acc[2][0]); acc[2][1] = fmaf(a2, bv.y, acc[2][1]);
            acc[2][2] = fmaf(a2, bv.z, acc[2][2]); acc[2][3] = fmaf(a2, bv.w, acc[2][3]);
            acc[3][0] = fmaf(a3, bv.x, acc[3][0]); acc[3][1] = fmaf(a3, bv.y, acc[3][1]);
            acc[3][2] = fmaf(a3, bv.z, acc[3][2]); acc[3][3] = fmaf(a3, bv.w, acc[3][3]);
        }
        __syncthreads();
    }

#pragma unroll
    for (int i = 0; i < 4; i++) {
        int r = rowBase + ty * 4 + i;
        if (r < M) {
            *(float4*)&C[(size_t)r * DOU + tx * 4] =
                make_float4(acc[i][0], acc[i][1], acc[i][2], acc[i][3]);
        }
    }
}

// ---------------------------------------------------------------------------
// SpMM d=64: y += vals[e] * x[col[e]]  scattered to row[e]. 16 threads/edge.
// dual: two (x,y) pairs sharing the same edge list
// ---------------------------------------------------------------------------
__global__ void spmm_dual(const int* __restrict__ row, const int* __restrict__ col,
                          const float* __restrict__ vals,
                          const float* __restrict__ x1, float* y1,
                          const float* __restrict__ x2, float* y2) {
    unsigned idx = blockIdx.x * blockDim.x + threadIdx.x;
    unsigned e = idx >> 4;
    if (e >= NE) return;
    int lane4 = (idx & 15) * 4;
    int r = row[e], c = col[e];
    float v = vals[e];

    const float4 a = *(const float4*)&x1[(size_t)c * DOU + lane4];
    float* p1 = &y1[(size_t)r * DOU + lane4];
    atomicAdd(p1 + 0, v * a.x); atomicAdd(p1 + 1, v * a.y);
    atomicAdd(p1 + 2, v * a.z); atomicAdd(p1 + 3, v * a.w);

    const float4 b = *(const float4*)&x2[(size_t)c * DOU + lane4];
    float* p2 = &y2[(size_t)r * DOU + lane4];
    atomicAdd(p2 + 0, v * b.x); atomicAdd(p2 + 1, v * b.y);
    atomicAdd(p2 + 2, v * b.z); atomicAdd(p2 + 3, v * b.w);
}

__global__ void spmm_single(const int* __restrict__ row, const int* __restrict__ col,
                            const float* __restrict__ vals,
                            const float* __restrict__ x1, float* y1) {
    unsigned idx = blockIdx.x * blockDim.x + threadIdx.x;
    unsigned e = idx >> 4;
    if (e >= NE) return;
    int lane4 = (idx & 15) * 4;
    int r = row[e], c = col[e];
    float v = vals[e];

    const float4 a = *(const float4*)&x1[(size_t)c * DOU + lane4];
    float* p1 = &y1[(size_t)r * DOU + lane4];
    atomicAdd(p1 + 0, v * a.x); atomicAdd(p1 + 1, v * a.y);
    atomicAdd(p1 + 2, v * a.z); atomicAdd(p1 + 3, v * a.w);
}

// ---------------------------------------------------------------------------
// Fused wide GEMM: h = T@W2 ; zinb = Z0@W2 -> mean = clip(exp), disp = clip(softplus)
// Block: 128 threads (one column each), 8 rows per block.
// grid = (1024/128, 20000/8) = (8, 2500)
// ---------------------------------------------------------------------------
__global__ void gemm_wide(const float* __restrict__ T, const float* __restrict__ Z0,
                          const float* __restrict__ W2,
                          float* __restrict__ hout, float* __restrict__ meanout,
                          float* __restrict__ dispout) {
    __shared__ float ts[8 * 64];
    __shared__ float zs[8 * 64];

    int tid = threadIdx.x;                 // 0..127
    int col = blockIdx.x * 128 + tid;      // 0..1023
    int rowBase = blockIdx.y * 8;

#pragma unroll
    for (int i = 0; i < 4; i++) {
        int idx = tid + i * 128;
        ts[idx] = T[(size_t)rowBase * DOU + idx];
        zs[idx] = Z0[(size_t)rowBase * DOU + idx];
    }
    __syncthreads();

    float acch[8], accz[8];
#pragma unroll
    for (int r = 0; r < 8; r++) { acch[r] = 0.f; accz[r] = 0.f; }

#pragma unroll
    for (int k0 = 0; k0 < 64; k0 += 4) {
        float w0 = W2[(size_t)(k0 + 0) * DIN + col];
        float w1 = W2[(size_t)(k0 + 1) * DIN + col];
        float w2 = W2[(size_t)(k0 + 2) * DIN + col];
        float w3 = W2[(size_t)(k0 + 3) * DIN + col];
#pragma unroll
        for (int r = 0; r < 8; r++) {
            float4 tv = *(float4*)&ts[r * 64 + k0];
            acch[r] = fmaf(tv.x, w0, acch[r]);
            acch[r] = fmaf(tv.y, w1, acch[r]);
            acch[r] = fmaf(tv.z, w2, acch[r]);
            acch[r] = fmaf(tv.w, w3, acch[r]);
            float4 zv = *(float4*)&zs[r * 64 + k0];
            accz[r] = fmaf(zv.x, w0, accz[r]);
            accz[r] = fmaf(zv.y, w1, accz[r]);
            accz[r] = fmaf(zv.z, w2, accz[r]);
            accz[r] = fmaf(zv.w, w3, accz[r]);
        }
    }

#pragma unroll
    for (int r = 0; r < 8; r++) {
        size_t o = (size_t)(rowBase + r) * DIN + col;
        hout[o] = acch[r];
        float x = accz[r];
        float m = fminf(fmaxf(expf(x), 1e-5f), 1e6f);
        meanout[o] = m;
        float sp = fmaxf(x, 0.f) + log1pf(expf(-fabsf(x)));   // stable softplus
        dispout[o] = fminf(fmaxf(sp, 1e-4f), 1e4f);
    }
}

// ---------------------------------------------------------------------------
// Bilinear discriminators, one warp per row, 8 rows per 256-thread block.
//   ret[i]   = relu(za)[i]^T W relu(z)[i]  + b
//   ret_a[i] = relu(zs)[i]^T W relu(za)[i] + b
// ---------------------------------------------------------------------------
__global__ void bilinear_k(const float* __restrict__ z, const float* __restrict__ za,
                           const float* __restrict__ zsv,
                           const float* __restrict__ W, const float* __restrict__ bptr,
                           float* __restrict__ ret, float* __restrict__ reta) {
    __shared__ float Ws[64 * 65];
    __shared__ float ce[8][64], ca[8][64], cs[8][64];

    int tid = threadIdx.x;
    for (int idx = tid; idx < 4096; idx += 256) {
        int d = idx >> 6, k = idx & 63;
        Ws[d * 65 + k] = W[idx];
    }

    int w = tid >> 5, lane = tid & 31;
    int rowb = blockIdx.x * 8 + w;

#pragma unroll
    for (int jj = 0; jj < 2; jj++) {
        int j = lane + jj * 32;
        ce[w][j] = fmaxf(z  [(size_t)rowb * DOU + j], 0.f);
        ca[w][j] = fmaxf(za [(size_t)rowb * DOU + j], 0.f);
        cs[w][j] = fmaxf(zsv[(size_t)rowb * DOU + j], 0.f);
    }
    __syncthreads();

    float r1 = 0.f, r2 = 0.f;
#pragma unroll
    for (int dd = 0; dd < 2; dd++) {
        int d = lane + dd * 32;
        float s1 = 0.f, s2 = 0.f;
#pragma unroll
        for (int k = 0; k < 64; k++) {
            float wv = Ws[d * 65 + k];
            s1 = fmaf(wv, ce[w][k], s1);
            s2 = fmaf(wv, ca[w][k], s2);
        }
        r1 = fmaf(ca[w][d], s1, r1);
        r2 = fmaf(cs[w][d], s2, r2);
    }
#pragma unroll
    for (int off = 16; off; off >>= 1) {
        r1 += __shfl_down_sync(0xffffffffu, r1, off);
        r2 += __shfl_down_sync(0xffffffffu, r2, off);
    }
    if (lane == 0) {
        float b = bptr[0];
        ret[rowb]  = r1 + b;
        reta[rowb] = r2 + b;
    }
}

// ---------------------------------------------------------------------------
extern "C" void kernel_launch(void* const* d_in, const int* in_sizes, int n_in,
                              void* d_out, int out_size) {
    const float* feat   = (const float*)d_in[0];
    const float* feat_a = (const float*)d_in[1];
    const int*   row    = (const int*)  d_in[2];
    const int*   col    = (const int*)  d_in[3];
    const float* vals   = (const float*)d_in[4];
    const int*   row_a  = (const int*)  d_in[5];
    const int*   col_a  = (const int*)  d_in[6];
    const float* vals_a = (const float*)d_in[7];
    const float* W1     = (const float*)d_in[8];
    const float* W2     = (const float*)d_in[9];
    const float* discW  = (const float*)d_in[10];
    const float* discB  = (const float*)d_in[11];

    float* out = (float*)d_out;
    float* z_out    = out + OFF_HIDEN;   // hiden_emb, accumulated in place
    float* h_out    = out + OFF_H;
    float* ret_out  = out + OFF_RET;
    float* reta_out = out + OFF_RETA;
    float* mean_out = out + OFF_MEAN;
    float* disp_out = out + OFF_DISP;

    float *p_z0, *p_za0, *p_zaacc, *p_zsacc, *p_t;
    cudaGetSymbolAddress((void**)&p_z0,    g_z0);
    cudaGetSymbolAddress((void**)&p_za0,   g_za0);
    cudaGetSymbolAddress((void**)&p_zaacc, g_zaacc);
    cudaGetSymbolAddress((void**)&p_zsacc, g_zsacc);
    cudaGetSymbolAddress((void**)&p_t,     g_t);

    // 1. zero accumulators (z region of d_out + 3 scratch accumulators + t)
    zero_kernel<<<512, 256>>>(z_out, p_zaacc, p_zsacc, p_t);

    // 2. z0 = feat @ W1 ; za0 = feat_a @ W1
    int gx = (NN + 63) / 64;
    gemm_in64<<<gx, 256>>>(feat,   W1, p_z0,  NN);
    gemm_in64<<<gx, 256>>>(feat_a, W1, p_za0, NN);

    // 3. z = A z0 (into d_out hiden region) ; za_acc = A za0
    spmm_dual<<<(NE * 16) / 256, 256>>>(row, col, vals, p_z0, z_out, p_za0, p_zaacc);

    // 4. zs_acc = A_a za0
    spmm_single<<<(NE * 16) / 256, 256>>>(row_a, col_a, vals_a, p_za0, p_zsacc);

    // 5. t = A z   (then h = t @ W2, replacing spmm(A, z@W2))
    spmm_single<<<(NE * 16) / 256, 256>>>(row, col, vals, z_out, p_t);

    // 6. h = t@W2 ; mean/disp from z0@W2 (fused)
    dim3 gw(DIN / 128, NN / 8);
    gemm_wide<<<gw, 128>>>(p_t, p_z0, W2, h_out, mean_out, disp_out);

    // 7. bilinear discriminators
    bilinear_k<<<NN / 8, 256>>>(z_out, p_zaacc, p_zsacc, discW, discB,
                                ret_out, reta_out);
}

// round 6
// speedup vs baseline: 1.2812x; 1.2812x over previous
#include <cuda_runtime.h>
#include <math.h>

#define NN   20000
#define DIN  1024
#define DOU  64
#define NE   320000
#define SZ   (NN*DOU)          // 1,280,000 floats per [N,64] buffer

// Output layout (flattened tuple, float32):
//   hiden_emb [N,64], h [N,1024], ret [N,1], ret_a [N,1], mean [N,1024], disp [N,1024]
#define OFF_HIDEN 0
#define OFF_H     ((size_t)SZ)
#define OFF_RET   (OFF_H + (size_t)NN*DIN)
#define OFF_RETA  (OFF_RET + NN)
#define OFF_MEAN  (OFF_RETA + NN)
#define OFF_DISP  (OFF_MEAN + (size_t)NN*DIN)

// Scratch: z0, za0, za_acc (emb_a pre-relu), zs_acc (emb_s pre-relu), t = A*z
__device__ float g_z0[SZ];
__device__ float g_za0[SZ];
__device__ float g_zaacc[SZ];
__device__ float g_zsacc[SZ];
__device__ float g_t[SZ];

// ---------------------------------------------------------------------------
// f32x2 packed-FMA helpers (FFMA2 — 2x FFMA throughput, PTX-only)
// ---------------------------------------------------------------------------
__device__ __forceinline__ void fma2(unsigned long long& d,
                                     unsigned long long a, unsigned long long b) {
    asm("fma.rn.f32x2 %0, %1, %2, %0;" : "+l"(d) : "l"(a), "l"(b));
}
__device__ __forceinline__ unsigned long long pack2(float x, float y) {
    unsigned long long r;
    asm("mov.b64 %0, {%1, %2};" : "=l"(r) : "f"(x), "f"(y));
    return r;
}
__device__ __forceinline__ void unpack2(unsigned long long v, float& lo, float& hi) {
    asm("mov.b64 {%0, %1}, %2;" : "=f"(lo), "=f"(hi) : "l"(v));
}
// vectorized global reduction: one L1tex wavefront instead of four
__device__ __forceinline__ void red4(float* p, float a, float b, float c, float d) {
    asm volatile("red.global.add.v4.f32 [%0], {%1,%2,%3,%4};"
                 :: "l"(p), "f"(a), "f"(b), "f"(c), "f"(d) : "memory");
}

// ---------------------------------------------------------------------------
// Zero the 4 atomically-accumulated buffers (vectorized)
// ---------------------------------------------------------------------------
__global__ void zero_kernel(float4* zout, float4* a, float4* b, float4* c) {
    int i = blockIdx.x * blockDim.x + threadIdx.x;
    int stride = gridDim.x * blockDim.x;
    const int n = SZ / 4;
    float4 z = make_float4(0.f, 0.f, 0.f, 0.f);
    for (int j = i; j < n; j += stride) {
        zout[j] = z; a[j] = z; b[j] = z; c[j] = z;
    }
}

// ---------------------------------------------------------------------------
// C[M,64] = A[M,1024] @ B[1024,64]
// BM=64, BN=64, BK=32, 128 threads, 8x4 micro-tile with f32x2 row-pair packing.
// As stored k-major so adjacent rows form free ulonglong2 (f32x2 pair) loads.
// ---------------------------------------------------------------------------
__global__ __launch_bounds__(128) void gemm_in64(const float* __restrict__ A,
                                                 const float* __restrict__ B,
                                                 float* __restrict__ C, int M) {
    __shared__ float As[32 * 64];   // [k][row]
    __shared__ float Bs[32 * 64];   // [k][col]

    int tid = threadIdx.x;
    int rowBase = blockIdx.x * 64;
    int tx = tid & 15;      // col group (4 cols)
    int ty = tid >> 4;      // row group (8 rows)

    unsigned long long acc[4][4];   // [row-pair][col], each packs 2 rows
#pragma unroll
    for (int i = 0; i < 4; i++)
#pragma unroll
        for (int j = 0; j < 4; j++) acc[i][j] = 0ull;

    int ar = tid >> 1;              // 0..63 row within tile
    int ak = (tid & 1) * 16;        // k offset 0 or 16
    bool aval = (rowBase + ar) < M;
    const float* arow = A + (size_t)(rowBase + ar) * DIN + ak;

    for (int k0 = 0; k0 < DIN; k0 += 32) {
        // A tile -> k-major smem (transpose on store)
#pragma unroll
        for (int j = 0; j < 4; j++) {
            float4 v = aval ? *(const float4*)(arow + k0 + 4 * j)
                            : make_float4(0.f, 0.f, 0.f, 0.f);
            int kb = ak + 4 * j;
            As[(kb + 0) * 64 + ar] = v.x;
            As[(kb + 1) * 64 + ar] = v.y;
            As[(kb + 2) * 64 + ar] = v.z;
            As[(kb + 3) * 64 + ar] = v.w;
        }
        // B tile (32x64, contiguous)
        const float4* bsrc = (const float4*)(B + (size_t)k0 * DOU);
#pragma unroll
        for (int j = 0; j < 4; j++)
            ((float4*)Bs)[tid + 128 * j] = bsrc[tid + 128 * j];

        __syncthreads();

#pragma unroll 8
        for (int kk = 0; kk < 32; kk++) {
            const ulonglong2* ap = (const ulonglong2*)&As[kk * 64 + ty * 8];
            ulonglong2 aA = ap[0];   // rows (0,1),(2,3)
            ulonglong2 aB = ap[1];   // rows (4,5),(6,7)
            float4 bv = *(const float4*)&Bs[kk * 64 + tx * 4];
            unsigned long long b0 = pack2(bv.x, bv.x);
            unsigned long long b1 = pack2(bv.y, bv.y);
            unsigned long long b2 = pack2(bv.z, bv.z);
            unsigned long long b3 = pack2(bv.w, bv.w);
            fma2(acc[0][0], aA.x, b0); fma2(acc[0][1], aA.x, b1);
            fma2(acc[0][2], aA.x, b2); fma2(acc[0][3], aA.x, b3);
            fma2(acc[1][0], aA.y, b0); fma2(acc[1][1], aA.y, b1);
            fma2(acc[1][2], aA.y, b2); fma2(acc[1][3], aA.y, b3);
            fma2(acc[2][0], aB.x, b0); fma2(acc[2][1], aB.x, b1);
            fma2(acc[2][2], aB.x, b2); fma2(acc[2][3], aB.x, b3);
            fma2(acc[3][0], aB.y, b0); fma2(acc[3][1], aB.y, b1);
            fma2(acc[3][2], aB.y, b2); fma2(acc[3][3], aB.y, b3);
        }
        __syncthreads();
    }

#pragma unroll
    for (int rp = 0; rp < 4; rp++) {
        float l0, h0, l1, h1, l2, h2, l3, h3;
        unpack2(acc[rp][0], l0, h0);
        unpack2(acc[rp][1], l1, h1);
        unpack2(acc[rp][2], l2, h2);
        unpack2(acc[rp][3], l3, h3);
        int r0 = rowBase + ty * 8 + rp * 2;
        if (r0 < M)
            *(float4*)&C[(size_t)r0 * DOU + tx * 4] = make_float4(l0, l1, l2, l3);
        if (r0 + 1 < M)
            *(float4*)&C[(size_t)(r0 + 1) * DOU + tx * 4] = make_float4(h0, h1, h2, h3);
    }
}

// ---------------------------------------------------------------------------
// SpMM d=64: y += vals[e] * x[col[e]] scattered to row[e]. 16 threads/edge,
// one red.global.add.v4.f32 per thread per target.
// ---------------------------------------------------------------------------
__global__ void spmm_dual(const int* __restrict__ row, const int* __restrict__ col,
                          const float* __restrict__ vals,
                          const float* __restrict__ x1, float* y1,
                          const float* __restrict__ x2, float* y2) {
    unsigned idx = blockIdx.x * blockDim.x + threadIdx.x;
    unsigned e = idx >> 4;
    if (e >= NE) return;
    int lane4 = (idx & 15) << 2;
    int r = __ldg(&row[e]), c = __ldg(&col[e]);
    float v = __ldg(&vals[e]);

    const float4 a = __ldg((const float4*)&x1[(size_t)c * DOU + lane4]);
    red4(&y1[(size_t)r * DOU + lane4], v * a.x, v * a.y, v * a.z, v * a.w);

    const float4 b = __ldg((const float4*)&x2[(size_t)c * DOU + lane4]);
    red4(&y2[(size_t)r * DOU + lane4], v * b.x, v * b.y, v * b.z, v * b.w);
}

__global__ void spmm_single(const int* __restrict__ row, const int* __restrict__ col,
                            const float* __restrict__ vals,
                            const float* __restrict__ x1, float* y1) {
    unsigned idx = blockIdx.x * blockDim.x + threadIdx.x;
    unsigned e = idx >> 4;
    if (e >= NE) return;
    int lane4 = (idx & 15) << 2;
    int r = __ldg(&row[e]), c = __ldg(&col[e]);
    float v = __ldg(&vals[e]);

    const float4 a = __ldg((const float4*)&x1[(size_t)c * DOU + lane4]);
    red4(&y1[(size_t)r * DOU + lane4], v * a.x, v * a.y, v * a.z, v * a.w);
}

// ---------------------------------------------------------------------------
// Fused wide GEMM: h = T@W2 ; zinb = Z0@W2 -> mean = clip(exp), disp = clip(softplus)
// 128 threads (one col each), 16 rows/block, f32x2 k-pair packing,
// streaming stores (outputs never re-read).
// grid = (1024/128, 20000/16) = (8, 1250)
// ---------------------------------------------------------------------------
__global__ __launch_bounds__(128) void gemm_wide(const float* __restrict__ T,
                                                 const float* __restrict__ Z0,
                                                 const float* __restrict__ W2,
                                                 float* __restrict__ hout,
                                                 float* __restrict__ meanout,
                                                 float* __restrict__ dispout) {
    __shared__ float ts[16 * 64];
    __shared__ float zs[16 * 64];

    int tid = threadIdx.x;                 // 0..127
    int col = blockIdx.x * 128 + tid;      // 0..1023
    int rowBase = blockIdx.y * 16;

    const float4* tsrc = (const float4*)(T  + (size_t)rowBase * DOU);
    const float4* zsrc = (const float4*)(Z0 + (size_t)rowBase * DOU);
#pragma unroll
    for (int i = 0; i < 2; i++) {
        ((float4*)ts)[tid + 128 * i] = tsrc[tid + 128 * i];
        ((float4*)zs)[tid + 128 * i] = zsrc[tid + 128 * i];
    }
    __syncthreads();

    unsigned long long acch[16], accz[16];
#pragma unroll
    for (int r = 0; r < 16; r++) { acch[r] = 0ull; accz[r] = 0ull; }

#pragma unroll
    for (int k0 = 0; k0 < 64; k0 += 4) {
        float w0 = W2[(size_t)(k0 + 0) * DIN + col];
        float w1 = W2[(size_t)(k0 + 1) * DIN + col];
        float w2 = W2[(size_t)(k0 + 2) * DIN + col];
        float w3 = W2[(size_t)(k0 + 3) * DIN + col];
        unsigned long long wp0 = pack2(w0, w1);
        unsigned long long wp1 = pack2(w2, w3);
#pragma unroll
        for (int r = 0; r < 16; r++) {
            ulonglong2 tv = *(const ulonglong2*)&ts[r * 64 + k0];
            fma2(acch[r], tv.x, wp0);
            fma2(acch[r], tv.y, wp1);
            ulonglong2 zv = *(const ulonglong2*)&zs[r * 64 + k0];
            fma2(accz[r], zv.x, wp0);
            fma2(accz[r], zv.y, wp1);
        }
    }

#pragma unroll
    for (int r = 0; r < 16; r++) {
        size_t o = (size_t)(rowBase + r) * DIN + col;
        float lo, hi;
        unpack2(acch[r], lo, hi);
        __stcs(&hout[o], lo + hi);
        unpack2(accz[r], lo, hi);
        float x = lo + hi;
        __stcs(&meanout[o], fminf(fmaxf(__expf(x), 1e-5f), 1e6f));
        float sp = fmaxf(x, 0.f) + __logf(1.f + __expf(-fabsf(x)));
        __stcs(&dispout[o], fminf(fmaxf(sp, 1e-4f), 1e4f));
    }
}

// ---------------------------------------------------------------------------
// Bilinear discriminators, one warp per row, 8 rows per 256-thread block.
//   ret[i]   = relu(za)[i]^T W relu(z)[i]  + b
//   ret_a[i] = relu(zs)[i]^T W relu(za)[i] + b
// ---------------------------------------------------------------------------
__global__ void bilinear_k(const float* __restrict__ z, const float* __restrict__ za,
                           const float* __restrict__ zsv,
                           const float* __restrict__ W, const float* __restrict__ bptr,
                           float* __restrict__ ret, float* __restrict__ reta) {
    __shared__ float Ws[64 * 65];
    __shared__ float ce[8][64], ca[8][64], cs[8][64];

    int tid = threadIdx.x;
    for (int idx = tid; idx < 4096; idx += 256) {
        int d = idx >> 6, k = idx & 63;
        Ws[d * 65 + k] = W[idx];
    }

    int w = tid >> 5, lane = tid & 31;
    int rowb = blockIdx.x * 8 + w;

#pragma unroll
    for (int jj = 0; jj < 2; jj++) {
        int j = lane + jj * 32;
        ce[w][j] = fmaxf(z  [(size_t)rowb * DOU + j], 0.f);
        ca[w][j] = fmaxf(za [(size_t)rowb * DOU + j], 0.f);
        cs[w][j] = fmaxf(zsv[(size_t)rowb * DOU + j], 0.f);
    }
    __syncthreads();

    float r1 = 0.f, r2 = 0.f;
#pragma unroll
    for (int dd = 0; dd < 2; dd++) {
        int d = lane + dd * 32;
        float s1 = 0.f, s2 = 0.f;
#pragma unroll
        for (int k = 0; k < 64; k++) {
            float wv = Ws[d * 65 + k];
            s1 = fmaf(wv, ce[w][k], s1);
            s2 = fmaf(wv, ca[w][k], s2);
        }
        r1 = fmaf(ca[w][d], s1, r1);
        r2 = fmaf(cs[w][d], s2, r2);
    }
#pragma unroll
    for (int off = 16; off; off >>= 1) {
        r1 += __shfl_down_sync(0xffffffffu, r1, off);
        r2 += __shfl_down_sync(0xffffffffu, r2, off);
    }
    if (lane == 0) {
        float b = bptr[0];
        ret[rowb]  = r1 + b;
        reta[rowb] = r2 + b;
    }
}

// ---------------------------------------------------------------------------
extern "C" void kernel_launch(void* const* d_in, const int* in_sizes, int n_in,
                              void* d_out, int out_size) {
    const float* feat   = (const float*)d_in[0];
    const float* feat_a = (const float*)d_in[1];
    const int*   row    = (const int*)  d_in[2];
    const int*   col    = (const int*)  d_in[3];
    const float* vals   = (const float*)d_in[4];
    const int*   row_a  = (const int*)  d_in[5];
    const int*   col_a  = (const int*)  d_in[6];
    const float* vals_a = (const float*)d_in[7];
    const float* W1     = (const float*)d_in[8];
    const float* W2     = (const float*)d_in[9];
    const float* discW  = (const float*)d_in[10];
    const float* discB  = (const float*)d_in[11];

    float* out = (float*)d_out;
    float* z_out    = out + OFF_HIDEN;   // hiden_emb, accumulated in place
    float* h_out    = out + OFF_H;
    float* ret_out  = out + OFF_RET;
    float* reta_out = out + OFF_RETA;
    float* mean_out = out + OFF_MEAN;
    float* disp_out = out + OFF_DISP;

    float *p_z0, *p_za0, *p_zaacc, *p_zsacc, *p_t;
    cudaGetSymbolAddress((void**)&p_z0,    g_z0);
    cudaGetSymbolAddress((void**)&p_za0,   g_za0);
    cudaGetSymbolAddress((void**)&p_zaacc, g_zaacc);
    cudaGetSymbolAddress((void**)&p_zsacc, g_zsacc);
    cudaGetSymbolAddress((void**)&p_t,     g_t);

    // 1. zero accumulators (z region of d_out + 2 scratch accumulators + t)
    zero_kernel<<<512, 256>>>((float4*)z_out, (float4*)p_zaacc,
                              (float4*)p_zsacc, (float4*)p_t);

    // 2. z0 = feat @ W1 ; za0 = feat_a @ W1
    int gx = (NN + 63) / 64;
    gemm_in64<<<gx, 128>>>(feat,   W1, p_z0,  NN);
    gemm_in64<<<gx, 128>>>(feat_a, W1, p_za0, NN);

    // 3. z = A z0 (into d_out hiden region) ; za_acc = A za0
    spmm_dual<<<(NE * 16) / 256, 256>>>(row, col, vals, p_z0, z_out, p_za0, p_zaacc);

    // 4. zs_acc = A_a za0
    spmm_single<<<(NE * 16) / 256, 256>>>(row_a, col_a, vals_a, p_za0, p_zsacc);

    // 5. t = A z   (then h = t @ W2, replacing spmm(A, z@W2))
    spmm_single<<<(NE * 16) / 256, 256>>>(row, col, vals, z_out, p_t);

    // 6. h = t@W2 ; mean/disp from z0@W2 (fused)
    dim3 gw(DIN / 128, NN / 16);
    gemm_wide<<<gw, 128>>>(p_t, p_z0, W2, h_out, mean_out, disp_out);

    // 7. bilinear discriminators
    bilinear_k<<<NN / 8, 256>>>(z_out, p_zaacc, p_zsacc, discW, discB,
                                ret_out, reta_out);
}